// round 11
// baseline (speedup 1.0000x reference)
#include <cuda_runtime.h>
#include <math.h>
#include <stdint.h>

#define VOCAB 32000
#define DIM   1024
#define NBITS 15
#define NTOK  4096
#define KDIM  1024
#define KP    512      // u32 bf16-pairs per row

#define OFF_BIT   4194304u
#define OFF_LOGIT 8388608u
#define OFF_LW    (8388608u + 131072000u)

// Pre-split bf16 hi/lo scratch (packed k-pairs as u32). Zero-init bss.
__device__ uint32_t d_Ah[(size_t)NTOK * KP];
__device__ uint32_t d_Al[(size_t)NTOK * KP];
__device__ uint32_t d_Bh[(size_t)VOCAB * KP];
__device__ uint32_t d_Bl[(size_t)VOCAB * KP];

// ---------------------------------------------------------------------------
// bf16 split helpers
// ---------------------------------------------------------------------------
__device__ __forceinline__ uint32_t cvt_bf16x2(float hi, float lo) {
    uint32_t u;
    asm("cvt.rn.bf16x2.f32 %0, %1, %2;" : "=r"(u) : "f"(hi), "f"(lo));
    return u;
}
__device__ __forceinline__ void split4(float4 v, uint2& h, uint2& l) {
    h.x = cvt_bf16x2(v.y, v.x);
    h.y = cvt_bf16x2(v.w, v.z);
    float f0 = __uint_as_float(h.x << 16);
    float f1 = __uint_as_float(h.x & 0xffff0000u);
    float f2 = __uint_as_float(h.y << 16);
    float f3 = __uint_as_float(h.y & 0xffff0000u);
    l.x = cvt_bf16x2(v.y - f1, v.x - f0);
    l.y = cvt_bf16x2(v.w - f3, v.z - f2);
}

// split pre-pass: one float4 per thread -> uint2 hi + uint2 lo
__global__ void split_kernel(const float* __restrict__ src,
                             uint32_t* __restrict__ dh,
                             uint32_t* __restrict__ dl)
{
    int idx = blockIdx.x * blockDim.x + threadIdx.x;   // float4 index
    float4 v = reinterpret_cast<const float4*>(src)[idx];
    uint2 h, l;
    split4(v, h, l);
    *reinterpret_cast<uint2*>(dh + (size_t)idx * 2) = h;
    *reinterpret_cast<uint2*>(dl + (size_t)idx * 2) = l;
}

// ---------------------------------------------------------------------------
// 1) id_emb
// ---------------------------------------------------------------------------
__global__ void id_embed_kernel(const int* __restrict__ ids,
                                const float* __restrict__ weight,
                                float* __restrict__ out)
{
    int idx = blockIdx.x * blockDim.x + threadIdx.x;
    int token = idx >> 8;
    int d4    = idx & 255;
    int id    = ids[token];
    id = min(max(id, 0), VOCAB - 1);
    const float4* src = reinterpret_cast<const float4*>(weight + (size_t)id * DIM);
    reinterpret_cast<float4*>(out)[idx] = src[d4];
}

// ---------------------------------------------------------------------------
// 2) bit_emb
// ---------------------------------------------------------------------------
__global__ void bit_embed_kernel(const int* __restrict__ ids,
                                 const float* __restrict__ wbit,
                                 float* __restrict__ out)
{
    int idx = blockIdx.x * blockDim.x + threadIdx.x;
    int token = idx >> 8;
    int d4    = idx & 255;
    int id    = ids[token];
    id = min(max(id, 0), VOCAB - 1);
    const float4* wb = reinterpret_cast<const float4*>(wbit);
    float4 acc = make_float4(0.f, 0.f, 0.f, 0.f);
#pragma unroll
    for (int j = 0; j < NBITS; j++) {
        float4 w = wb[j * 256 + d4];
        float s = ((id >> (14 - j)) & 1) ? 1.0f : -1.0f;
        acc.x += s * w.x; acc.y += s * w.y; acc.z += s * w.z; acc.w += s * w.w;
    }
    reinterpret_cast<float4*>(out)[idx] = acc;
}

// ---------------------------------------------------------------------------
// 3) GEMM: 3-pass split-bf16 m16n8k16 mma, fed by pre-split scratch.
//    Block 128x128, BK=16 (8 u32 pairs), 8 warps (warp tile 64x32).
//    SMEM stride 12 u32/row; fragments via ldmatrix.
// ---------------------------------------------------------------------------
#define SSTR 12

__device__ __forceinline__ void mma_bf16(float* c, const uint32_t* a, const uint32_t* b) {
    asm volatile(
        "mma.sync.aligned.m16n8k16.row.col.f32.bf16.bf16.f32 "
        "{%0,%1,%2,%3},{%4,%5,%6,%7},{%8,%9},{%0,%1,%2,%3};"
        : "+f"(c[0]), "+f"(c[1]), "+f"(c[2]), "+f"(c[3])
        : "r"(a[0]), "r"(a[1]), "r"(a[2]), "r"(a[3]), "r"(b[0]), "r"(b[1]));
}
__device__ __forceinline__ void ldsm_x4(uint32_t* r, uint32_t addr) {
    asm volatile("ldmatrix.sync.aligned.m8n8.x4.shared.b16 {%0,%1,%2,%3}, [%4];"
        : "=r"(r[0]), "=r"(r[1]), "=r"(r[2]), "=r"(r[3]) : "r"(addr));
}
__device__ __forceinline__ void ldsm_x2(uint32_t* r, uint32_t addr) {
    asm volatile("ldmatrix.sync.aligned.m8n8.x2.shared.b16 {%0,%1}, [%2];"
        : "=r"(r[0]), "=r"(r[1]) : "r"(addr));
}
__device__ __forceinline__ uint32_t smem_u32(const void* p) {
    uint32_t a;
    asm("{ .reg .u64 t; cvta.to.shared.u64 t, %1; cvt.u32.u64 %0, t; }"
        : "=r"(a) : "l"(p));
    return a;
}

__global__ __launch_bounds__(256)
void bf16x3_gemm_kernel(float* __restrict__ C)   // [4096, 32000]
{
    __shared__ __align__(16) uint32_t sAh[2][128 * SSTR];
    __shared__ __align__(16) uint32_t sAl[2][128 * SSTR];
    __shared__ __align__(16) uint32_t sBh[2][128 * SSTR];
    __shared__ __align__(16) uint32_t sBl[2][128 * SSTR];

    const int tid  = threadIdx.x;
    const int lane = tid & 31;
    const int warp = tid >> 5;
    const int wm   = (warp & 1) * 64;
    const int wn   = (warp >> 1) * 32;
    const int g    = lane >> 2;
    const int t    = lane & 3;

    const int mBase = blockIdx.y * 128;
    const int nBase = blockIdx.x * 128;

    // staging: thread -> (row = tid>>1 in 0..127, u32-half = (tid&1)*4)
    const int srow  = tid >> 1;
    const int sh4   = (tid & 1) * 4;
    const uint32_t* gAh = d_Ah + (size_t)(mBase + srow) * KP + sh4;
    const uint32_t* gAl = d_Al + (size_t)(mBase + srow) * KP + sh4;
    const uint32_t* gBh = d_Bh + (size_t)(nBase + srow) * KP + sh4;
    const uint32_t* gBl = d_Bl + (size_t)(nBase + srow) * KP + sh4;
    const int sOff = srow * SSTR + sh4;

    // ldmatrix per-lane address offsets (bytes), computed once
    // A (x4): matrices [r0-7,k0-7],[r8-15,k0-7],[r0-7,k8-15],[r8-15,k8-15]
    const int aq = lane >> 3;
    const int aRow = (lane & 7) + ((aq & 1) << 3);
    const int aCol = (aq >> 1) << 2;
    int aoff[4];
#pragma unroll
    for (int mf = 0; mf < 4; mf++)
        aoff[mf] = ((wm + mf * 16 + aRow) * SSTR + aCol) * 4;
    // B (x2): matrices [n0-7,k0-7],[n0-7,k8-15]; lanes 0-15 supply addrs
    const int l2 = lane & 15;
    const int bRow = l2 & 7;
    const int bCol = (l2 >> 3) << 2;
    int boff[4];
#pragma unroll
    for (int nf = 0; nf < 4; nf++)
        boff[nf] = ((wn + nf * 8 + bRow) * SSTR + bCol) * 4;

    const uint32_t bAh = smem_u32(sAh), bAl = smem_u32(sAl);
    const uint32_t bBh = smem_u32(sBh), bBl = smem_u32(sBl);

    float acc[4][4][4];
#pragma unroll
    for (int i = 0; i < 4; i++)
#pragma unroll
        for (int j = 0; j < 4; j++)
#pragma unroll
            for (int q = 0; q < 4; q++) acc[i][j][q] = 0.f;

    // prologue: k-tile 0 -> stage 0
    {
        *reinterpret_cast<uint4*>(&sAh[0][sOff]) = *reinterpret_cast<const uint4*>(gAh);
        *reinterpret_cast<uint4*>(&sAl[0][sOff]) = *reinterpret_cast<const uint4*>(gAl);
        *reinterpret_cast<uint4*>(&sBh[0][sOff]) = *reinterpret_cast<const uint4*>(gBh);
        *reinterpret_cast<uint4*>(&sBl[0][sOff]) = *reinterpret_cast<const uint4*>(gBl);
    }
    __syncthreads();

    const int NSTEP = KP / 8;   // 64 k-tiles of 8 u32 pairs (BK=16 bf16)
    for (int kt = 0; kt < NSTEP; kt++) {
        const int buf = kt & 1;
        const uint32_t stg = buf * (uint32_t)(128 * SSTR * 4);

        uint4 vah, val, vbh, vbl;
        if (kt + 1 < NSTEP) {
            const int ko = (kt + 1) * 8;
            vah = *reinterpret_cast<const uint4*>(gAh + ko);
            val = *reinterpret_cast<const uint4*>(gAl + ko);
            vbh = *reinterpret_cast<const uint4*>(gBh + ko);
            vbl = *reinterpret_cast<const uint4*>(gBl + ko);
        }

        uint32_t afh[4][4], afl[4][4], bfh[4][2], bfl[4][2];
#pragma unroll
        for (int mf = 0; mf < 4; mf++) {
            ldsm_x4(afh[mf], bAh + stg + aoff[mf]);
            ldsm_x4(afl[mf], bAl + stg + aoff[mf]);
        }
#pragma unroll
        for (int nf = 0; nf < 4; nf++) {
            ldsm_x2(bfh[nf], bBh + stg + boff[nf]);
            ldsm_x2(bfl[nf], bBl + stg + boff[nf]);
        }

#pragma unroll
        for (int mf = 0; mf < 4; mf++)
#pragma unroll
            for (int nf = 0; nf < 4; nf++) {
                mma_bf16(acc[mf][nf], afh[mf], bfh[nf]);
                mma_bf16(acc[mf][nf], afh[mf], bfl[nf]);
                mma_bf16(acc[mf][nf], afl[mf], bfh[nf]);
            }

        if (kt + 1 < NSTEP) {
            const int nb = buf ^ 1;
            __syncthreads();
            *reinterpret_cast<uint4*>(&sAh[nb][sOff]) = vah;
            *reinterpret_cast<uint4*>(&sAl[nb][sOff]) = val;
            *reinterpret_cast<uint4*>(&sBh[nb][sOff]) = vbh;
            *reinterpret_cast<uint4*>(&sBl[nb][sOff]) = vbl;
            __syncthreads();
        }
    }

    // epilogue: c0:(g,2t) c1:(g,2t+1) c2:(g+8,2t) c3:(g+8,2t+1)
#pragma unroll
    for (int mf = 0; mf < 4; mf++) {
#pragma unroll
        for (int nf = 0; nf < 4; nf++) {
            const int row = mBase + wm + mf * 16 + g;
            const int col = nBase + wn + nf * 8 + t * 2;
            float* p0 = C + (size_t)row * VOCAB + col;
            float* p1 = C + (size_t)(row + 8) * VOCAB + col;
            *reinterpret_cast<float2*>(p0) = make_float2(acc[mf][nf][0], acc[mf][nf][1]);
            *reinterpret_cast<float2*>(p1) = make_float2(acc[mf][nf][2], acc[mf][nf][3]);
        }
    }
}

// ---------------------------------------------------------------------------
// 4) logit_w: softmax over 32000 + projection onto +-1 bit codes.
// ---------------------------------------------------------------------------
__global__ __launch_bounds__(256)
void softmax_bits_kernel(const float* __restrict__ logit,
                         float* __restrict__ out_lw)
{
    const int row = blockIdx.x;
    const int tid = threadIdx.x;
    const float* L = logit + (size_t)row * VOCAB;

    float m = -1e30f;
    for (int i = tid; i < VOCAB; i += 256) m = fmaxf(m, L[i]);
#pragma unroll
    for (int o = 16; o; o >>= 1) m = fmaxf(m, __shfl_xor_sync(0xffffffffu, m, o));
    __shared__ float wmax[8];
    if ((tid & 31) == 0) wmax[tid >> 5] = m;
    __syncthreads();
    m = wmax[0];
#pragma unroll
    for (int w = 1; w < 8; w++) m = fmaxf(m, wmax[w]);

    float s = 0.f;
    float bh[7] = {0.f, 0.f, 0.f, 0.f, 0.f, 0.f, 0.f};
    for (int t = 0; t < VOCAB / 256; t++) {
        float e = __expf(L[tid + (t << 8)] - m);
        s += e;
#pragma unroll
        for (int k = 0; k < 7; k++)
            bh[k] += ((t >> k) & 1) ? e : 0.f;
    }

    float bs[16];
#pragma unroll
    for (int k = 0; k < 8; k++) bs[k] = ((tid >> k) & 1) ? s : 0.f;
#pragma unroll
    for (int k = 0; k < 7; k++) bs[k + 8] = bh[k];
    bs[15] = s;

#pragma unroll
    for (int q = 0; q < 16; q++) {
#pragma unroll
        for (int o = 16; o; o >>= 1)
            bs[q] += __shfl_xor_sync(0xffffffffu, bs[q], o);
    }
    __shared__ float red[8][16];
    if ((tid & 31) == 0) {
#pragma unroll
        for (int q = 0; q < 16; q++) red[tid >> 5][q] = bs[q];
    }
    __syncthreads();
    if (tid == 0) {
        float tot[16];
#pragma unroll
        for (int q = 0; q < 16; q++) {
            float v = 0.f;
#pragma unroll
            for (int w = 0; w < 8; w++) v += red[w][q];
            tot[q] = v;
        }
        float inv = 1.0f / tot[15];
#pragma unroll
        for (int k = 0; k < 15; k++)
            out_lw[(size_t)row * NBITS + (14 - k)] = 2.0f * tot[k] * inv - 1.0f;
    }
}

// ---------------------------------------------------------------------------
extern "C" void kernel_launch(void* const* d_in, const int* in_sizes, int n_in,
                              void* d_out, int out_size)
{
    const int*   ids    = (const int*)  d_in[0];
    const float* tensor = (const float*)d_in[1];
    const float* weight = (const float*)d_in[2];
    const float* wbit   = (const float*)d_in[3];

    float* out     = (float*)d_out;
    float* id_emb  = out;
    float* bit_emb = out + OFF_BIT;
    float* logit   = out + OFF_LOGIT;
    float* lw      = out + OFF_LW;

    uint32_t *pAh, *pAl, *pBh, *pBl;
    cudaGetSymbolAddress((void**)&pAh, d_Ah);
    cudaGetSymbolAddress((void**)&pAl, d_Al);
    cudaGetSymbolAddress((void**)&pBh, d_Bh);
    cudaGetSymbolAddress((void**)&pBl, d_Bl);

    id_embed_kernel <<<4096, 256>>>(ids, weight, id_emb);
    bit_embed_kernel<<<4096, 256>>>(ids, wbit, bit_emb);

    // pre-split fp32 -> bf16 hi/lo pairs
    split_kernel<<<NTOK, 256>>>(tensor, pAh, pAl);     // 4096*256 float4
    split_kernel<<<VOCAB, 256>>>(weight, pBh, pBl);    // 32000*256 float4

    dim3 grid(VOCAB / 128, NTOK / 128);   // 250 x 32
    bf16x3_gemm_kernel<<<grid, 256>>>(logit);

    softmax_bits_kernel<<<NTOK, 256>>>(logit, lw);
}

// round 12
// speedup vs baseline: 1.0705x; 1.0705x over previous
#include <cuda_runtime.h>
#include <math.h>
#include <stdint.h>

#define VOCAB 32000
#define DIM   1024
#define NBITS 15
#define NTOK  4096
#define KDIM  1024
#define KP    512      // u32 bf16-pairs per row

#define OFF_BIT   4194304u
#define OFF_LOGIT 8388608u
#define OFF_LW    (8388608u + 131072000u)

// Pre-split bf16 hi/lo scratch (packed k-pairs as u32). Zero-init bss.
__device__ uint32_t d_Ah[(size_t)NTOK * KP];
__device__ uint32_t d_Al[(size_t)NTOK * KP];
__device__ uint32_t d_Bh[(size_t)VOCAB * KP];
__device__ uint32_t d_Bl[(size_t)VOCAB * KP];

// ---------------------------------------------------------------------------
// bf16 split helpers
// ---------------------------------------------------------------------------
__device__ __forceinline__ uint32_t cvt_bf16x2(float hi, float lo) {
    uint32_t u;
    asm("cvt.rn.bf16x2.f32 %0, %1, %2;" : "=r"(u) : "f"(hi), "f"(lo));
    return u;
}
__device__ __forceinline__ void split4(float4 v, uint2& h, uint2& l) {
    h.x = cvt_bf16x2(v.y, v.x);
    h.y = cvt_bf16x2(v.w, v.z);
    float f0 = __uint_as_float(h.x << 16);
    float f1 = __uint_as_float(h.x & 0xffff0000u);
    float f2 = __uint_as_float(h.y << 16);
    float f3 = __uint_as_float(h.y & 0xffff0000u);
    l.x = cvt_bf16x2(v.y - f1, v.x - f0);
    l.y = cvt_bf16x2(v.w - f3, v.z - f2);
}

__global__ void split_kernel(const float* __restrict__ src,
                             uint32_t* __restrict__ dh,
                             uint32_t* __restrict__ dl)
{
    int idx = blockIdx.x * blockDim.x + threadIdx.x;   // float4 index
    float4 v = reinterpret_cast<const float4*>(src)[idx];
    uint2 h, l;
    split4(v, h, l);
    *reinterpret_cast<uint2*>(dh + (size_t)idx * 2) = h;
    *reinterpret_cast<uint2*>(dl + (size_t)idx * 2) = l;
}

// ---------------------------------------------------------------------------
// 1) id_emb
// ---------------------------------------------------------------------------
__global__ void id_embed_kernel(const int* __restrict__ ids,
                                const float* __restrict__ weight,
                                float* __restrict__ out)
{
    int idx = blockIdx.x * blockDim.x + threadIdx.x;
    int token = idx >> 8;
    int d4    = idx & 255;
    int id    = ids[token];
    id = min(max(id, 0), VOCAB - 1);
    const float4* src = reinterpret_cast<const float4*>(weight + (size_t)id * DIM);
    reinterpret_cast<float4*>(out)[idx] = src[d4];
}

// ---------------------------------------------------------------------------
// 2) bit_emb
// ---------------------------------------------------------------------------
__global__ void bit_embed_kernel(const int* __restrict__ ids,
                                 const float* __restrict__ wbit,
                                 float* __restrict__ out)
{
    int idx = blockIdx.x * blockDim.x + threadIdx.x;
    int token = idx >> 8;
    int d4    = idx & 255;
    int id    = ids[token];
    id = min(max(id, 0), VOCAB - 1);
    const float4* wb = reinterpret_cast<const float4*>(wbit);
    float4 acc = make_float4(0.f, 0.f, 0.f, 0.f);
#pragma unroll
    for (int j = 0; j < NBITS; j++) {
        float4 w = wb[j * 256 + d4];
        float s = ((id >> (14 - j)) & 1) ? 1.0f : -1.0f;
        acc.x += s * w.x; acc.y += s * w.y; acc.z += s * w.z; acc.w += s * w.w;
    }
    reinterpret_cast<float4*>(out)[idx] = acc;
}

// ---------------------------------------------------------------------------
// 3) GEMM: 3-pass split-bf16 m16n8k16 mma, cp.async 4-stage pipeline.
//    Block 128x128, BK=16 (8 u32 pairs), 8 warps (warp tile 64x32).
//    SMEM row stride 12 u32 (48B): conflict-free LDSM. Grid (M=32, N=250)
//    with M fast-varying -> A pairs L2-resident, B streamed ~once.
// ---------------------------------------------------------------------------
#define SSTR      12
#define STAGES    4
#define ARR_BYTES (128 * SSTR * 4)       // 6144 per array
#define STG_BYTES (4 * ARR_BYTES)        // 24576 per stage
#define A_H 0
#define A_L ARR_BYTES
#define B_H (2 * ARR_BYTES)
#define B_L (3 * ARR_BYTES)
#define GEMM_SMEM (STAGES * STG_BYTES)   // 98304

__device__ __forceinline__ void mma_bf16(float* c, const uint32_t* a, const uint32_t* b) {
    asm volatile(
        "mma.sync.aligned.m16n8k16.row.col.f32.bf16.bf16.f32 "
        "{%0,%1,%2,%3},{%4,%5,%6,%7},{%8,%9},{%0,%1,%2,%3};"
        : "+f"(c[0]), "+f"(c[1]), "+f"(c[2]), "+f"(c[3])
        : "r"(a[0]), "r"(a[1]), "r"(a[2]), "r"(a[3]), "r"(b[0]), "r"(b[1]));
}
__device__ __forceinline__ void ldsm_x4(uint32_t* r, uint32_t addr) {
    asm volatile("ldmatrix.sync.aligned.m8n8.x4.shared.b16 {%0,%1,%2,%3}, [%4];"
        : "=r"(r[0]), "=r"(r[1]), "=r"(r[2]), "=r"(r[3]) : "r"(addr));
}
__device__ __forceinline__ void ldsm_x2(uint32_t* r, uint32_t addr) {
    asm volatile("ldmatrix.sync.aligned.m8n8.x2.shared.b16 {%0,%1}, [%2];"
        : "=r"(r[0]), "=r"(r[1]) : "r"(addr));
}
__device__ __forceinline__ uint32_t smem_u32(const void* p) {
    uint32_t a;
    asm("{ .reg .u64 t; cvta.to.shared.u64 t, %1; cvt.u32.u64 %0, t; }"
        : "=r"(a) : "l"(p));
    return a;
}
__device__ __forceinline__ void cp16(uint32_t dst, const void* src) {
    asm volatile("cp.async.cg.shared.global [%0], [%1], 16;" :: "r"(dst), "l"(src));
}

__global__ __launch_bounds__(256)
void bf16x3_gemm_kernel(float* __restrict__ C)   // [4096, 32000]
{
    extern __shared__ __align__(16) char smem[];
    const uint32_t sb = smem_u32(smem);

    const int tid  = threadIdx.x;
    const int lane = tid & 31;
    const int warp = tid >> 5;
    const int wm   = (warp & 1) * 64;
    const int wn   = (warp >> 1) * 32;
    const int g    = lane >> 2;
    const int t    = lane & 3;

    const int mBase = blockIdx.x * 128;   // M fast-varying in launch order
    const int nBase = blockIdx.y * 128;

    // cp.async staging: thread -> (row = tid>>1, 16B-half = tid&1)
    const int srow = tid >> 1;
    const int sh   = tid & 1;
    const uint32_t dstOff = (uint32_t)(srow * SSTR + sh * 4) * 4;   // bytes
    const uint32_t* gAh = d_Ah + (size_t)(mBase + srow) * KP + sh * 4;
    const uint32_t* gAl = d_Al + (size_t)(mBase + srow) * KP + sh * 4;
    const uint32_t* gBh = d_Bh + (size_t)(nBase + srow) * KP + sh * 4;
    const uint32_t* gBl = d_Bl + (size_t)(nBase + srow) * KP + sh * 4;

    // ldmatrix per-lane address offsets (bytes) — mapping verified (R11 rel_err)
    const int aq = lane >> 3;
    const int aRow = (lane & 7) + ((aq & 1) << 3);
    const int aCol = (aq >> 1) << 2;
    int aoff[4];
#pragma unroll
    for (int mf = 0; mf < 4; mf++)
        aoff[mf] = ((wm + mf * 16 + aRow) * SSTR + aCol) * 4;
    const int l2 = lane & 15;
    const int bRow = l2 & 7;
    const int bCol = (l2 >> 3) << 2;
    int boff[4];
#pragma unroll
    for (int nf = 0; nf < 4; nf++)
        boff[nf] = ((wn + nf * 8 + bRow) * SSTR + bCol) * 4;

    float acc[4][4][4];
#pragma unroll
    for (int i = 0; i < 4; i++)
#pragma unroll
        for (int j = 0; j < 4; j++)
#pragma unroll
            for (int q = 0; q < 4; q++) acc[i][j][q] = 0.f;

    // prologue: stages 0..2 in flight
#pragma unroll
    for (int s = 0; s < STAGES - 1; s++) {
        const uint32_t db = sb + s * STG_BYTES;
        const int ko = s * 8;
        cp16(db + A_H + dstOff, gAh + ko);
        cp16(db + A_L + dstOff, gAl + ko);
        cp16(db + B_H + dstOff, gBh + ko);
        cp16(db + B_L + dstOff, gBl + ko);
        asm volatile("cp.async.commit_group;" ::: "memory");
    }

    const int NSTEP = KP / 8;   // 64
    for (int kt = 0; kt < NSTEP; kt++) {
        asm volatile("cp.async.wait_group %0;" :: "n"(STAGES - 2) : "memory");
        __syncthreads();   // stage kt visible to all; all warps done with kt-1

        // issue stage kt+3 into slot (kt+3)&3 (overwrites finished kt-1 slot)
        if (kt + STAGES - 1 < NSTEP) {
            const uint32_t db = sb + ((kt + STAGES - 1) & (STAGES - 1)) * STG_BYTES;
            const int ko = (kt + STAGES - 1) * 8;
            cp16(db + A_H + dstOff, gAh + ko);
            cp16(db + A_L + dstOff, gAl + ko);
            cp16(db + B_H + dstOff, gBh + ko);
            cp16(db + B_L + dstOff, gBl + ko);
        }
        asm volatile("cp.async.commit_group;" ::: "memory");   // always (group counting)

        // compute slot kt&3
        const uint32_t db = sb + (kt & (STAGES - 1)) * STG_BYTES;
        uint32_t afh[4][4], afl[4][4], bfh[4][2], bfl[4][2];
#pragma unroll
        for (int mf = 0; mf < 4; mf++) {
            ldsm_x4(afh[mf], db + A_H + aoff[mf]);
            ldsm_x4(afl[mf], db + A_L + aoff[mf]);
        }
#pragma unroll
        for (int nf = 0; nf < 4; nf++) {
            ldsm_x2(bfh[nf], db + B_H + boff[nf]);
            ldsm_x2(bfl[nf], db + B_L + boff[nf]);
        }
#pragma unroll
        for (int mf = 0; mf < 4; mf++)
#pragma unroll
            for (int nf = 0; nf < 4; nf++) {
                mma_bf16(acc[mf][nf], afh[mf], bfh[nf]);
                mma_bf16(acc[mf][nf], afh[mf], bfl[nf]);
                mma_bf16(acc[mf][nf], afl[mf], bfh[nf]);
            }
    }

    // epilogue: c0:(g,2t) c1:(g,2t+1) c2:(g+8,2t) c3:(g+8,2t+1)
#pragma unroll
    for (int mf = 0; mf < 4; mf++) {
#pragma unroll
        for (int nf = 0; nf < 4; nf++) {
            const int row = mBase + wm + mf * 16 + g;
            const int col = nBase + wn + nf * 8 + t * 2;
            float* p0 = C + (size_t)row * VOCAB + col;
            float* p1 = C + (size_t)(row + 8) * VOCAB + col;
            *reinterpret_cast<float2*>(p0) = make_float2(acc[mf][nf][0], acc[mf][nf][1]);
            *reinterpret_cast<float2*>(p1) = make_float2(acc[mf][nf][2], acc[mf][nf][3]);
        }
    }
}

// ---------------------------------------------------------------------------
// 4) logit_w: softmax over 32000 + projection onto +-1 bit codes.
// ---------------------------------------------------------------------------
__global__ __launch_bounds__(256)
void softmax_bits_kernel(const float* __restrict__ logit,
                         float* __restrict__ out_lw)
{
    const int row = blockIdx.x;
    const int tid = threadIdx.x;
    const float* L = logit + (size_t)row * VOCAB;

    float m = -1e30f;
    for (int i = tid; i < VOCAB; i += 256) m = fmaxf(m, L[i]);
#pragma unroll
    for (int o = 16; o; o >>= 1) m = fmaxf(m, __shfl_xor_sync(0xffffffffu, m, o));
    __shared__ float wmax[8];
    if ((tid & 31) == 0) wmax[tid >> 5] = m;
    __syncthreads();
    m = wmax[0];
#pragma unroll
    for (int w = 1; w < 8; w++) m = fmaxf(m, wmax[w]);

    float s = 0.f;
    float bh[7] = {0.f, 0.f, 0.f, 0.f, 0.f, 0.f, 0.f};
    for (int t = 0; t < VOCAB / 256; t++) {
        float e = __expf(L[tid + (t << 8)] - m);
        s += e;
#pragma unroll
        for (int k = 0; k < 7; k++)
            bh[k] += ((t >> k) & 1) ? e : 0.f;
    }

    float bs[16];
#pragma unroll
    for (int k = 0; k < 8; k++) bs[k] = ((tid >> k) & 1) ? s : 0.f;
#pragma unroll
    for (int k = 0; k < 7; k++) bs[k + 8] = bh[k];
    bs[15] = s;

#pragma unroll
    for (int q = 0; q < 16; q++) {
#pragma unroll
        for (int o = 16; o; o >>= 1)
            bs[q] += __shfl_xor_sync(0xffffffffu, bs[q], o);
    }
    __shared__ float red[8][16];
    if ((tid & 31) == 0) {
#pragma unroll
        for (int q = 0; q < 16; q++) red[tid >> 5][q] = bs[q];
    }
    __syncthreads();
    if (tid == 0) {
        float tot[16];
#pragma unroll
        for (int q = 0; q < 16; q++) {
            float v = 0.f;
#pragma unroll
            for (int w = 0; w < 8; w++) v += red[w][q];
            tot[q] = v;
        }
        float inv = 1.0f / tot[15];
#pragma unroll
        for (int k = 0; k < 15; k++)
            out_lw[(size_t)row * NBITS + (14 - k)] = 2.0f * tot[k] * inv - 1.0f;
    }
}

// ---------------------------------------------------------------------------
extern "C" void kernel_launch(void* const* d_in, const int* in_sizes, int n_in,
                              void* d_out, int out_size)
{
    const int*   ids    = (const int*)  d_in[0];
    const float* tensor = (const float*)d_in[1];
    const float* weight = (const float*)d_in[2];
    const float* wbit   = (const float*)d_in[3];

    float* out     = (float*)d_out;
    float* id_emb  = out;
    float* bit_emb = out + OFF_BIT;
    float* logit   = out + OFF_LOGIT;
    float* lw      = out + OFF_LW;

    uint32_t *pAh, *pAl, *pBh, *pBl;
    cudaGetSymbolAddress((void**)&pAh, d_Ah);
    cudaGetSymbolAddress((void**)&pAl, d_Al);
    cudaGetSymbolAddress((void**)&pBh, d_Bh);
    cudaGetSymbolAddress((void**)&pBl, d_Bl);

    id_embed_kernel <<<4096, 256>>>(ids, weight, id_emb);
    bit_embed_kernel<<<4096, 256>>>(ids, wbit, bit_emb);

    split_kernel<<<NTOK, 256>>>(tensor, pAh, pAl);
    split_kernel<<<VOCAB, 256>>>(weight, pBh, pBl);

    cudaFuncSetAttribute(bf16x3_gemm_kernel,
                         cudaFuncAttributeMaxDynamicSharedMemorySize, GEMM_SMEM);
    dim3 grid(NTOK / 128, VOCAB / 128);   // (32 M, 250 N), M fast -> B panel reuse
    bf16x3_gemm_kernel<<<grid, 256, GEMM_SMEM>>>(logit);

    softmax_bits_kernel<<<NTOK, 256>>>(logit, lw);
}

// round 13
// speedup vs baseline: 1.9661x; 1.8366x over previous
#include <cuda_runtime.h>
#include <math.h>
#include <stdint.h>

#define VOCAB 32000
#define DIM   1024
#define NBITS 15
#define NTOK  4096
#define KDIM  1024

#define OFF_BIT   4194304u
#define OFF_LOGIT 8388608u
#define OFF_LW    (8388608u + 131072000u)

// ---------------------------------------------------------------------------
// 1) id_emb
// ---------------------------------------------------------------------------
__global__ void id_embed_kernel(const int* __restrict__ ids,
                                const float* __restrict__ weight,
                                float* __restrict__ out)
{
    int idx = blockIdx.x * blockDim.x + threadIdx.x;
    int token = idx >> 8;
    int d4    = idx & 255;
    int id    = ids[token];
    id = min(max(id, 0), VOCAB - 1);
    const float4* src = reinterpret_cast<const float4*>(weight + (size_t)id * DIM);
    reinterpret_cast<float4*>(out)[idx] = src[d4];
}

// ---------------------------------------------------------------------------
// 2) bit_emb
// ---------------------------------------------------------------------------
__global__ void bit_embed_kernel(const int* __restrict__ ids,
                                 const float* __restrict__ wbit,
                                 float* __restrict__ out)
{
    int idx = blockIdx.x * blockDim.x + threadIdx.x;
    int token = idx >> 8;
    int d4    = idx & 255;
    int id    = ids[token];
    id = min(max(id, 0), VOCAB - 1);
    const float4* wb = reinterpret_cast<const float4*>(wbit);
    float4 acc = make_float4(0.f, 0.f, 0.f, 0.f);
#pragma unroll
    for (int j = 0; j < NBITS; j++) {
        float4 w = wb[j * 256 + d4];
        float s = ((id >> (14 - j)) & 1) ? 1.0f : -1.0f;
        acc.x += s * w.x; acc.y += s * w.y; acc.z += s * w.z; acc.w += s * w.w;
    }
    reinterpret_cast<float4*>(out)[idx] = acc;
}

// ---------------------------------------------------------------------------
// 3) GEMM: 3-pass split-bf16 m16n8k16 mma (R8 structure: in-loop split +
//    register-staged double buffer), with ldmatrix fragment loads and
//    M-fast rasterization (A panel L2-resident, B streamed ~once).
//    Block 128x128, BK=16 bf16 (8 u32 pairs), 8 warps (warp tile 64x32).
// ---------------------------------------------------------------------------
#define SSTR 12   // u32 stride per SMEM row (8 data + 4 pad)

__device__ __forceinline__ uint32_t cvt_bf16x2(float hi, float lo) {
    uint32_t u;
    asm("cvt.rn.bf16x2.f32 %0, %1, %2;" : "=r"(u) : "f"(hi), "f"(lo));
    return u;
}
__device__ __forceinline__ void split4(float4 v, uint2& h, uint2& l) {
    h.x = cvt_bf16x2(v.y, v.x);
    h.y = cvt_bf16x2(v.w, v.z);
    float f0 = __uint_as_float(h.x << 16);
    float f1 = __uint_as_float(h.x & 0xffff0000u);
    float f2 = __uint_as_float(h.y << 16);
    float f3 = __uint_as_float(h.y & 0xffff0000u);
    l.x = cvt_bf16x2(v.y - f1, v.x - f0);
    l.y = cvt_bf16x2(v.w - f3, v.z - f2);
}
__device__ __forceinline__ void mma_bf16(float* c, const uint32_t* a, const uint32_t* b) {
    asm volatile(
        "mma.sync.aligned.m16n8k16.row.col.f32.bf16.bf16.f32 "
        "{%0,%1,%2,%3},{%4,%5,%6,%7},{%8,%9},{%0,%1,%2,%3};"
        : "+f"(c[0]), "+f"(c[1]), "+f"(c[2]), "+f"(c[3])
        : "r"(a[0]), "r"(a[1]), "r"(a[2]), "r"(a[3]), "r"(b[0]), "r"(b[1]));
}
__device__ __forceinline__ void ldsm_x4(uint32_t* r, uint32_t addr) {
    asm volatile("ldmatrix.sync.aligned.m8n8.x4.shared.b16 {%0,%1,%2,%3}, [%4];"
        : "=r"(r[0]), "=r"(r[1]), "=r"(r[2]), "=r"(r[3]) : "r"(addr));
}
__device__ __forceinline__ void ldsm_x2(uint32_t* r, uint32_t addr) {
    asm volatile("ldmatrix.sync.aligned.m8n8.x2.shared.b16 {%0,%1}, [%2];"
        : "=r"(r[0]), "=r"(r[1]) : "r"(addr));
}
__device__ __forceinline__ uint32_t smem_u32(const void* p) {
    uint32_t a;
    asm("{ .reg .u64 t; cvta.to.shared.u64 t, %1; cvt.u32.u64 %0, t; }"
        : "=r"(a) : "l"(p));
    return a;
}

__global__ __launch_bounds__(256)
void bf16x3_gemm_kernel(const float* __restrict__ A,   // [4096, 1024]
                        const float* __restrict__ B,   // [32000, 1024]
                        float* __restrict__ C)         // [4096, 32000]
{
    __shared__ __align__(16) uint32_t sAh[2][128 * SSTR];
    __shared__ __align__(16) uint32_t sAl[2][128 * SSTR];
    __shared__ __align__(16) uint32_t sBh[2][128 * SSTR];
    __shared__ __align__(16) uint32_t sBl[2][128 * SSTR];

    const int tid  = threadIdx.x;
    const int lane = tid & 31;
    const int warp = tid >> 5;
    const int wm   = (warp & 1) * 64;
    const int wn   = (warp >> 1) * 32;
    const int g    = lane >> 2;
    const int t    = lane & 3;

    const int mBase = blockIdx.x * 128;   // M fast-varying: B panel shared by wave
    const int nBase = blockIdx.y * 128;

    // Staging (R8): thread owns rows (tid>>2) and (tid>>2)+64, float4 #(tid&3)
    const int row0 = tid >> 2;          // 0..63
    const int c4   = tid & 3;
    const float* Ag0 = A + (size_t)(mBase + row0) * KDIM + c4 * 4;
    const float* Ag1 = A + (size_t)(mBase + row0 + 64) * KDIM + c4 * 4;
    const float* Bg0 = B + (size_t)(nBase + row0) * KDIM + c4 * 4;
    const float* Bg1 = B + (size_t)(nBase + row0 + 64) * KDIM + c4 * 4;
    const int s0 = row0 * SSTR + c4 * 2;
    const int s1 = (row0 + 64) * SSTR + c4 * 2;

    // ldmatrix per-lane byte offsets (mapping verified bit-exact in R11/R12)
    const int aq = lane >> 3;
    const int aRow = (lane & 7) + ((aq & 1) << 3);
    const int aCol = (aq >> 1) << 2;
    int aoff[4];
#pragma unroll
    for (int mf = 0; mf < 4; mf++)
        aoff[mf] = ((wm + mf * 16 + aRow) * SSTR + aCol) * 4;
    const int l2 = lane & 15;
    const int bRow = l2 & 7;
    const int bCol = (l2 >> 3) << 2;
    int boff[4];
#pragma unroll
    for (int nf = 0; nf < 4; nf++)
        boff[nf] = ((wn + nf * 8 + bRow) * SSTR + bCol) * 4;

    const uint32_t bAh = smem_u32(sAh), bAl = smem_u32(sAl);
    const uint32_t bBh = smem_u32(sBh), bBl = smem_u32(sBl);

    float acc[4][4][4];
#pragma unroll
    for (int i = 0; i < 4; i++)
#pragma unroll
        for (int j = 0; j < 4; j++)
#pragma unroll
            for (int q = 0; q < 4; q++) acc[i][j][q] = 0.f;

    // prologue: k-tile 0 -> stage 0 (split in-line, R8 style)
    {
        float4 a0 = *reinterpret_cast<const float4*>(Ag0);
        float4 a1 = *reinterpret_cast<const float4*>(Ag1);
        float4 b0 = *reinterpret_cast<const float4*>(Bg0);
        float4 b1 = *reinterpret_cast<const float4*>(Bg1);
        uint2 h, l;
        split4(a0, h, l);
        *reinterpret_cast<uint2*>(&sAh[0][s0]) = h; *reinterpret_cast<uint2*>(&sAl[0][s0]) = l;
        split4(a1, h, l);
        *reinterpret_cast<uint2*>(&sAh[0][s1]) = h; *reinterpret_cast<uint2*>(&sAl[0][s1]) = l;
        split4(b0, h, l);
        *reinterpret_cast<uint2*>(&sBh[0][s0]) = h; *reinterpret_cast<uint2*>(&sBl[0][s0]) = l;
        split4(b1, h, l);
        *reinterpret_cast<uint2*>(&sBh[0][s1]) = h; *reinterpret_cast<uint2*>(&sBl[0][s1]) = l;
    }
    __syncthreads();

    const int NSTEP = KDIM / 16;   // 64
    for (int kt = 0; kt < NSTEP; kt++) {
        const int buf = kt & 1;
        const uint32_t stg = (uint32_t)buf * (128 * SSTR * 4);

        float4 a0, a1, b0, b1;
        if (kt + 1 < NSTEP) {
            const int ko = (kt + 1) * 16;
            a0 = *reinterpret_cast<const float4*>(Ag0 + ko);
            a1 = *reinterpret_cast<const float4*>(Ag1 + ko);
            b0 = *reinterpret_cast<const float4*>(Bg0 + ko);
            b1 = *reinterpret_cast<const float4*>(Bg1 + ko);
        }

        // fragment loads via ldmatrix (was 48 scalar LDS)
        uint32_t afh[4][4], afl[4][4], bfh[4][2], bfl[4][2];
#pragma unroll
        for (int mf = 0; mf < 4; mf++) {
            ldsm_x4(afh[mf], bAh + stg + aoff[mf]);
            ldsm_x4(afl[mf], bAl + stg + aoff[mf]);
        }
#pragma unroll
        for (int nf = 0; nf < 4; nf++) {
            ldsm_x2(bfh[nf], bBh + stg + boff[nf]);
            ldsm_x2(bfl[nf], bBl + stg + boff[nf]);
        }

#pragma unroll
        for (int mf = 0; mf < 4; mf++)
#pragma unroll
            for (int nf = 0; nf < 4; nf++) {
                mma_bf16(acc[mf][nf], afh[mf], bfh[nf]);
                mma_bf16(acc[mf][nf], afh[mf], bfl[nf]);
                mma_bf16(acc[mf][nf], afl[mf], bfh[nf]);
            }

        if (kt + 1 < NSTEP) {
            const int nb = buf ^ 1;
            uint2 ha0, la0, ha1, la1, hb0, lb0, hb1, lb1;
            split4(a0, ha0, la0); split4(a1, ha1, la1);
            split4(b0, hb0, lb0); split4(b1, hb1, lb1);
            __syncthreads();   // all warps done reading stage nb (from kt-1)
            *reinterpret_cast<uint2*>(&sAh[nb][s0]) = ha0; *reinterpret_cast<uint2*>(&sAl[nb][s0]) = la0;
            *reinterpret_cast<uint2*>(&sAh[nb][s1]) = ha1; *reinterpret_cast<uint2*>(&sAl[nb][s1]) = la1;
            *reinterpret_cast<uint2*>(&sBh[nb][s0]) = hb0; *reinterpret_cast<uint2*>(&sBl[nb][s0]) = lb0;
            *reinterpret_cast<uint2*>(&sBh[nb][s1]) = hb1; *reinterpret_cast<uint2*>(&sBl[nb][s1]) = lb1;
            __syncthreads();
        }
    }

    // epilogue: c0:(g,2t) c1:(g,2t+1) c2:(g+8,2t) c3:(g+8,2t+1)
#pragma unroll
    for (int mf = 0; mf < 4; mf++) {
#pragma unroll
        for (int nf = 0; nf < 4; nf++) {
            const int row = mBase + wm + mf * 16 + g;
            const int col = nBase + wn + nf * 8 + t * 2;
            float* p0 = C + (size_t)row * VOCAB + col;
            float* p1 = C + (size_t)(row + 8) * VOCAB + col;
            *reinterpret_cast<float2*>(p0) = make_float2(acc[mf][nf][0], acc[mf][nf][1]);
            *reinterpret_cast<float2*>(p1) = make_float2(acc[mf][nf][2], acc[mf][nf][3]);
        }
    }
}

// ---------------------------------------------------------------------------
// 4) logit_w: softmax over 32000 + projection onto +-1 bit codes.
// ---------------------------------------------------------------------------
__global__ __launch_bounds__(256)
void softmax_bits_kernel(const float* __restrict__ logit,
                         float* __restrict__ out_lw)
{
    const int row = blockIdx.x;
    const int tid = threadIdx.x;
    const float* L = logit + (size_t)row * VOCAB;

    float m = -1e30f;
    for (int i = tid; i < VOCAB; i += 256) m = fmaxf(m, L[i]);
#pragma unroll
    for (int o = 16; o; o >>= 1) m = fmaxf(m, __shfl_xor_sync(0xffffffffu, m, o));
    __shared__ float wmax[8];
    if ((tid & 31) == 0) wmax[tid >> 5] = m;
    __syncthreads();
    m = wmax[0];
#pragma unroll
    for (int w = 1; w < 8; w++) m = fmaxf(m, wmax[w]);

    float s = 0.f;
    float bh[7] = {0.f, 0.f, 0.f, 0.f, 0.f, 0.f, 0.f};
    for (int t = 0; t < VOCAB / 256; t++) {
        float e = __expf(L[tid + (t << 8)] - m);
        s += e;
#pragma unroll
        for (int k = 0; k < 7; k++)
            bh[k] += ((t >> k) & 1) ? e : 0.f;
    }

    float bs[16];
#pragma unroll
    for (int k = 0; k < 8; k++) bs[k] = ((tid >> k) & 1) ? s : 0.f;
#pragma unroll
    for (int k = 0; k < 7; k++) bs[k + 8] = bh[k];
    bs[15] = s;

#pragma unroll
    for (int q = 0; q < 16; q++) {
#pragma unroll
        for (int o = 16; o; o >>= 1)
            bs[q] += __shfl_xor_sync(0xffffffffu, bs[q], o);
    }
    __shared__ float red[8][16];
    if ((tid & 31) == 0) {
#pragma unroll
        for (int q = 0; q < 16; q++) red[tid >> 5][q] = bs[q];
    }
    __syncthreads();
    if (tid == 0) {
        float tot[16];
#pragma unroll
        for (int q = 0; q < 16; q++) {
            float v = 0.f;
#pragma unroll
            for (int w = 0; w < 8; w++) v += red[w][q];
            tot[q] = v;
        }
        float inv = 1.0f / tot[15];
#pragma unroll
        for (int k = 0; k < 15; k++)
            out_lw[(size_t)row * NBITS + (14 - k)] = 2.0f * tot[k] * inv - 1.0f;
    }
}

// ---------------------------------------------------------------------------
extern "C" void kernel_launch(void* const* d_in, const int* in_sizes, int n_in,
                              void* d_out, int out_size)
{
    const int*   ids    = (const int*)  d_in[0];
    const float* tensor = (const float*)d_in[1];
    const float* weight = (const float*)d_in[2];
    const float* wbit   = (const float*)d_in[3];

    float* out     = (float*)d_out;
    float* id_emb  = out;
    float* bit_emb = out + OFF_BIT;
    float* logit   = out + OFF_LOGIT;
    float* lw      = out + OFF_LW;

    id_embed_kernel <<<4096, 256>>>(ids, weight, id_emb);
    bit_embed_kernel<<<4096, 256>>>(ids, wbit, bit_emb);

    dim3 grid(NTOK / 128, VOCAB / 128);   // (32 M fast, 250 N): A L2-resident
    bf16x3_gemm_kernel<<<grid, 256>>>(tensor, weight, logit);

    softmax_bits_kernel<<<NTOK, 256>>>(logit, lw);
}

// round 15
// speedup vs baseline: 2.0584x; 1.0469x over previous
#include <cuda_runtime.h>
#include <math.h>
#include <stdint.h>

#define VOCAB 32000
#define DIM   1024
#define NBITS 15
#define NTOK  4096
#define KDIM  1024

#define OFF_BIT   4194304u
#define OFF_LOGIT 8388608u
#define OFF_LW    (8388608u + 131072000u)

// ---------------------------------------------------------------------------
// 1) id_emb
// ---------------------------------------------------------------------------
__global__ void id_embed_kernel(const int* __restrict__ ids,
                                const float* __restrict__ weight,
                                float* __restrict__ out)
{
    int idx = blockIdx.x * blockDim.x + threadIdx.x;
    int token = idx >> 8;
    int d4    = idx & 255;
    int id    = ids[token];
    id = min(max(id, 0), VOCAB - 1);
    const float4* src = reinterpret_cast<const float4*>(weight + (size_t)id * DIM);
    reinterpret_cast<float4*>(out)[idx] = src[d4];
}

// ---------------------------------------------------------------------------
// 2) bit_emb
// ---------------------------------------------------------------------------
__global__ void bit_embed_kernel(const int* __restrict__ ids,
                                 const float* __restrict__ wbit,
                                 float* __restrict__ out)
{
    int idx = blockIdx.x * blockDim.x + threadIdx.x;
    int token = idx >> 8;
    int d4    = idx & 255;
    int id    = ids[token];
    id = min(max(id, 0), VOCAB - 1);
    const float4* wb = reinterpret_cast<const float4*>(wbit);
    float4 acc = make_float4(0.f, 0.f, 0.f, 0.f);
#pragma unroll
    for (int j = 0; j < NBITS; j++) {
        float4 w = wb[j * 256 + d4];
        float s = ((id >> (14 - j)) & 1) ? 1.0f : -1.0f;
        acc.x += s * w.x; acc.y += s * w.y; acc.z += s * w.z; acc.w += s * w.w;
    }
    reinterpret_cast<float4*>(out)[idx] = acc;
}

// ---------------------------------------------------------------------------
// 3) GEMM: 3-pass split-bf16 m16n8k16 mma. R13 structure with:
//    - single __syncthreads per k-step (pre-store sync proven redundant)
//    - B fragments via ldsm.x4 pairs (12 LDSM/iter instead of 16)
//    Block 128x128, BK=16, 8 warps (warp tile 64x32), M-fast raster.
// ---------------------------------------------------------------------------
#define SSTR 12   // u32 stride per SMEM row (8 data + 4 pad)

__device__ __forceinline__ uint32_t cvt_bf16x2(float hi, float lo) {
    uint32_t u;
    asm("cvt.rn.bf16x2.f32 %0, %1, %2;" : "=r"(u) : "f"(hi), "f"(lo));
    return u;
}
__device__ __forceinline__ void split4(float4 v, uint2& h, uint2& l) {
    h.x = cvt_bf16x2(v.y, v.x);
    h.y = cvt_bf16x2(v.w, v.z);
    float f0 = __uint_as_float(h.x << 16);
    float f1 = __uint_as_float(h.x & 0xffff0000u);
    float f2 = __uint_as_float(h.y << 16);
    float f3 = __uint_as_float(h.y & 0xffff0000u);
    l.x = cvt_bf16x2(v.y - f1, v.x - f0);
    l.y = cvt_bf16x2(v.w - f3, v.z - f2);
}
__device__ __forceinline__ void mma_bf16(float* c, const uint32_t* a, const uint32_t* b) {
    asm volatile(
        "mma.sync.aligned.m16n8k16.row.col.f32.bf16.bf16.f32 "
        "{%0,%1,%2,%3},{%4,%5,%6,%7},{%8,%9},{%0,%1,%2,%3};"
        : "+f"(c[0]), "+f"(c[1]), "+f"(c[2]), "+f"(c[3])
        : "r"(a[0]), "r"(a[1]), "r"(a[2]), "r"(a[3]), "r"(b[0]), "r"(b[1]));
}
__device__ __forceinline__ void ldsm_x4(uint32_t* r, uint32_t addr) {
    asm volatile("ldmatrix.sync.aligned.m8n8.x4.shared.b16 {%0,%1,%2,%3}, [%4];"
        : "=r"(r[0]), "=r"(r[1]), "=r"(r[2]), "=r"(r[3]) : "r"(addr));
}
__device__ __forceinline__ uint32_t smem_u32(const void* p) {
    uint32_t a;
    asm("{ .reg .u64 t; cvta.to.shared.u64 t, %1; cvt.u32.u64 %0, t; }"
        : "=r"(a) : "l"(p));
    return a;
}

__global__ __launch_bounds__(256)
void bf16x3_gemm_kernel(const float* __restrict__ A,   // [4096, 1024]
                        const float* __restrict__ B,   // [32000, 1024]
                        float* __restrict__ C)         // [4096, 32000]
{
    __shared__ __align__(16) uint32_t sAh[2][128 * SSTR];
    __shared__ __align__(16) uint32_t sAl[2][128 * SSTR];
    __shared__ __align__(16) uint32_t sBh[2][128 * SSTR];
    __shared__ __align__(16) uint32_t sBl[2][128 * SSTR];

    const int tid  = threadIdx.x;
    const int lane = tid & 31;
    const int warp = tid >> 5;
    const int wm   = (warp & 1) * 64;
    const int wn   = (warp >> 1) * 32;
    const int g    = lane >> 2;
    const int t    = lane & 3;

    const int mBase = blockIdx.x * 128;   // M fast-varying
    const int nBase = blockIdx.y * 128;

    // Staging: thread owns rows (tid>>2) and (tid>>2)+64, float4 #(tid&3)
    const int row0 = tid >> 2;
    const int c4   = tid & 3;
    const float* Ag0 = A + (size_t)(mBase + row0) * KDIM + c4 * 4;
    const float* Ag1 = A + (size_t)(mBase + row0 + 64) * KDIM + c4 * 4;
    const float* Bg0 = B + (size_t)(nBase + row0) * KDIM + c4 * 4;
    const float* Bg1 = B + (size_t)(nBase + row0 + 64) * KDIM + c4 * 4;
    const int s0 = row0 * SSTR + c4 * 2;
    const int s1 = (row0 + 64) * SSTR + c4 * 2;

    // A ldmatrix offsets (verified mapping): x4 = [r0-7,k0],[r8-15,k0],[r0-7,k8],[r8-15,k8]
    const int aq = lane >> 3;
    const int aRow = (lane & 7) + ((aq & 1) << 3);
    const int aCol = (aq >> 1) << 2;
    int aoff[4];
#pragma unroll
    for (int mf = 0; mf < 4; mf++)
        aoff[mf] = ((wm + mf * 16 + aRow) * SSTR + aCol) * 4;

    // B ldmatrix x4 pair offsets: pair p covers nf=2p,2p+1 (16 rows x both k-halves)
    // m0:(rows p16+0-7, k0-7) m1:(same rows, k8-15) m2:(rows+8, k0-7) m3:(rows+8, k8-15)
    const int bq = lane >> 3;
    const int bRow = (lane & 7) + ((bq >> 1) << 3);
    const int bCol = (bq & 1) << 2;
    int boff[2];
#pragma unroll
    for (int p = 0; p < 2; p++)
        boff[p] = ((wn + p * 16 + bRow) * SSTR + bCol) * 4;

    const uint32_t bAh = smem_u32(sAh), bAl = smem_u32(sAl);
    const uint32_t bBh = smem_u32(sBh), bBl = smem_u32(sBl);

    float acc[4][4][4];
#pragma unroll
    for (int i = 0; i < 4; i++)
#pragma unroll
        for (int j = 0; j < 4; j++)
#pragma unroll
            for (int q = 0; q < 4; q++) acc[i][j][q] = 0.f;

    // prologue: k-tile 0 -> stage 0
    {
        float4 a0 = *reinterpret_cast<const float4*>(Ag0);
        float4 a1 = *reinterpret_cast<const float4*>(Ag1);
        float4 b0 = *reinterpret_cast<const float4*>(Bg0);
        float4 b1 = *reinterpret_cast<const float4*>(Bg1);
        uint2 h, l;
        split4(a0, h, l);
        *reinterpret_cast<uint2*>(&sAh[0][s0]) = h; *reinterpret_cast<uint2*>(&sAl[0][s0]) = l;
        split4(a1, h, l);
        *reinterpret_cast<uint2*>(&sAh[0][s1]) = h; *reinterpret_cast<uint2*>(&sAl[0][s1]) = l;
        split4(b0, h, l);
        *reinterpret_cast<uint2*>(&sBh[0][s0]) = h; *reinterpret_cast<uint2*>(&sBl[0][s0]) = l;
        split4(b1, h, l);
        *reinterpret_cast<uint2*>(&sBh[0][s1]) = h; *reinterpret_cast<uint2*>(&sBl[0][s1]) = l;
    }
    __syncthreads();

    const int NSTEP = KDIM / 16;   // 64
    for (int kt = 0; kt < NSTEP; kt++) {
        const int buf = kt & 1;
        const uint32_t stg = (uint32_t)buf * (128 * SSTR * 4);

        float4 a0, a1, b0, b1;
        if (kt + 1 < NSTEP) {
            const int ko = (kt + 1) * 16;
            a0 = *reinterpret_cast<const float4*>(Ag0 + ko);
            a1 = *reinterpret_cast<const float4*>(Ag1 + ko);
            b0 = *reinterpret_cast<const float4*>(Bg0 + ko);
            b1 = *reinterpret_cast<const float4*>(Bg1 + ko);
        }

        // fragment loads: 8 x4 for A (hi+lo), 4 x4 for B (hi+lo, nf-pairs)
        uint32_t afh[4][4], afl[4][4], bph[2][4], bpl[2][4];
#pragma unroll
        for (int mf = 0; mf < 4; mf++) {
            ldsm_x4(afh[mf], bAh + stg + aoff[mf]);
            ldsm_x4(afl[mf], bAl + stg + aoff[mf]);
        }
#pragma unroll
        for (int p = 0; p < 2; p++) {
            ldsm_x4(bph[p], bBh + stg + boff[p]);
            ldsm_x4(bpl[p], bBl + stg + boff[p]);
        }

        // bph[p] regs: {nf=2p frag0, nf=2p frag1, nf=2p+1 frag0, nf=2p+1 frag1}
#pragma unroll
        for (int mf = 0; mf < 4; mf++)
#pragma unroll
            for (int nf = 0; nf < 4; nf++) {
                const uint32_t* bh = &bph[nf >> 1][(nf & 1) * 2];
                const uint32_t* bl = &bpl[nf >> 1][(nf & 1) * 2];
                mma_bf16(acc[mf][nf], afh[mf], bh);
                mma_bf16(acc[mf][nf], afh[mf], bl);
                mma_bf16(acc[mf][nf], afl[mf], bh);
            }

        if (kt + 1 < NSTEP) {
            const int nb = buf ^ 1;
            uint2 ha0, la0, ha1, la1, hb0, lb0, hb1, lb1;
            split4(a0, ha0, la0); split4(a1, ha1, la1);
            split4(b0, hb0, lb0); split4(b1, hb1, lb1);
            // stores target nb: no live readers (nb's last readers sealed by
            // the sync at the end of iteration kt-1) -> no pre-store sync.
            *reinterpret_cast<uint2*>(&sAh[nb][s0]) = ha0; *reinterpret_cast<uint2*>(&sAl[nb][s0]) = la0;
            *reinterpret_cast<uint2*>(&sAh[nb][s1]) = ha1; *reinterpret_cast<uint2*>(&sAl[nb][s1]) = la1;
            *reinterpret_cast<uint2*>(&sBh[nb][s0]) = hb0; *reinterpret_cast<uint2*>(&sBl[nb][s0]) = lb0;
            *reinterpret_cast<uint2*>(&sBh[nb][s1]) = hb1; *reinterpret_cast<uint2*>(&sBl[nb][s1]) = lb1;
            __syncthreads();
        }
    }

    // epilogue: c0:(g,2t) c1:(g,2t+1) c2:(g+8,2t) c3:(g+8,2t+1)
#pragma unroll
    for (int mf = 0; mf < 4; mf++) {
#pragma unroll
        for (int nf = 0; nf < 4; nf++) {
            const int row = mBase + wm + mf * 16 + g;
            const int col = nBase + wn + nf * 8 + t * 2;
            float* p0 = C + (size_t)row * VOCAB + col;
            float* p1 = C + (size_t)(row + 8) * VOCAB + col;
            *reinterpret_cast<float2*>(p0) = make_float2(acc[mf][nf][0], acc[mf][nf][1]);
            *reinterpret_cast<float2*>(p1) = make_float2(acc[mf][nf][2], acc[mf][nf][3]);
        }
    }
}

// ---------------------------------------------------------------------------
// 4) logit_w: softmax over 32000 + projection onto +-1 bit codes.
// ---------------------------------------------------------------------------
__global__ __launch_bounds__(256)
void softmax_bits_kernel(const float* __restrict__ logit,
                         float* __restrict__ out_lw)
{
    const int row = blockIdx.x;
    const int tid = threadIdx.x;
    const float* L = logit + (size_t)row * VOCAB;

    float m = -1e30f;
    for (int i = tid; i < VOCAB; i += 256) m = fmaxf(m, L[i]);
#pragma unroll
    for (int o = 16; o; o >>= 1) m = fmaxf(m, __shfl_xor_sync(0xffffffffu, m, o));
    __shared__ float wmax[8];
    if ((tid & 31) == 0) wmax[tid >> 5] = m;
    __syncthreads();
    m = wmax[0];
#pragma unroll
    for (int w = 1; w < 8; w++) m = fmaxf(m, wmax[w]);

    float s = 0.f;
    float bh[7] = {0.f, 0.f, 0.f, 0.f, 0.f, 0.f, 0.f};
    for (int t = 0; t < VOCAB / 256; t++) {
        float e = __expf(L[tid + (t << 8)] - m);
        s += e;
#pragma unroll
        for (int k = 0; k < 7; k++)
            bh[k] += ((t >> k) & 1) ? e : 0.f;
    }

    float bs[16];
#pragma unroll
    for (int k = 0; k < 8; k++) bs[k] = ((tid >> k) & 1) ? s : 0.f;
#pragma unroll
    for (int k = 0; k < 7; k++) bs[k + 8] = bh[k];
    bs[15] = s;

#pragma unroll
    for (int q = 0; q < 16; q++) {
#pragma unroll
        for (int o = 16; o; o >>= 1)
            bs[q] += __shfl_xor_sync(0xffffffffu, bs[q], o);
    }
    __shared__ float red[8][16];
    if ((tid & 31) == 0) {
#pragma unroll
        for (int q = 0; q < 16; q++) red[tid >> 5][q] = bs[q];
    }
    __syncthreads();
    if (tid == 0) {
        float tot[16];
#pragma unroll
        for (int q = 0; q < 16; q++) {
            float v = 0.f;
#pragma unroll
            for (int w = 0; w < 8; w++) v += red[w][q];
            tot[q] = v;
        }
        float inv = 1.0f / tot[15];
#pragma unroll
        for (int k = 0; k < 15; k++)
            out_lw[(size_t)row * NBITS + (14 - k)] = 2.0f * tot[k] * inv - 1.0f;
    }
}

// ---------------------------------------------------------------------------
extern "C" void kernel_launch(void* const* d_in, const int* in_sizes, int n_in,
                              void* d_out, int out_size)
{
    const int*   ids    = (const int*)  d_in[0];
    const float* tensor = (const float*)d_in[1];
    const float* weight = (const float*)d_in[2];
    const float* wbit   = (const float*)d_in[3];

    float* out     = (float*)d_out;
    float* id_emb  = out;
    float* bit_emb = out + OFF_BIT;
    float* logit   = out + OFF_LOGIT;
    float* lw      = out + OFF_LW;

    id_embed_kernel <<<4096, 256>>>(ids, weight, id_emb);
    bit_embed_kernel<<<4096, 256>>>(ids, wbit, bit_emb);

    dim3 grid(NTOK / 128, VOCAB / 128);   // (32 M fast, 250 N): A L2-resident
    bf16x3_gemm_kernel<<<grid, 256>>>(tensor, weight, logit);

    softmax_bits_kernel<<<NTOK, 256>>>(logit, lw);
}